// round 17
// baseline (speedup 1.0000x reference)
#include <cuda_runtime.h>
#include <math.h>
#include <stdint.h>

#define NN 50000
#define NE 800000
#define CIN 64
#define KDIM 192   // HID*C_IN
#define COUT 128
#define TOTN (2 * NN)
#define TOTE (2 * NE)
#define NB ((TOTN + 1023) / 1024)   // 98 scan blocks

typedef unsigned long long ull;

// ---- static scratch (no allocations allowed) ----
__device__ int   g_count[TOTN];
__device__ int   g_start[TOTN + 1];
__device__ int   g_cursor[TOTN];
__device__ int   g_partial[128];
__device__ int   g_done;
__device__ int2  g_se_sorted[TOTE];                     // (src, eid) 12.8 MB
__device__ float g_aggr[(size_t)TOTN * KDIM];           // 76.8 MB

// ---------- f32x2 / misc helpers ----------
__device__ __forceinline__ ull pack2(float lo, float hi) {
    ull r; asm("mov.b64 %0, {%1,%2};" : "=l"(r) : "f"(lo), "f"(hi)); return r;
}
__device__ __forceinline__ void unpack2(ull v, float& lo, float& hi) {
    asm("mov.b64 {%0,%1}, %2;" : "=f"(lo), "=f"(hi) : "l"(v));
}
__device__ __forceinline__ void fma2(ull& d, ull a, ull b) {
    asm("fma.rn.f32x2 %0, %1, %2, %0;" : "+l"(d) : "l"(a), "l"(b));
}
__device__ __forceinline__ ull relu2(ull v) {
    float lo, hi;
    unpack2(v, lo, hi);
    return pack2(fmaxf(lo, 0.f), fmaxf(hi, 0.f));
}
__device__ __forceinline__ float tanh_fast(float v) {
    float r; asm("tanh.approx.f32 %0, %1;" : "=f"(r) : "f"(v)); return r;
}
__device__ __forceinline__ uint32_t f2tf32(float f) {
    uint32_t u; asm("cvt.rna.tf32.f32 %0, %1;" : "=r"(u) : "f"(f)); return u;
}
__device__ __forceinline__ void mma_tf32(float* c, const uint32_t* a, const uint32_t* b) {
    asm("mma.sync.aligned.m16n8k8.row.col.f32.tf32.tf32.f32 "
        "{%0,%1,%2,%3}, {%4,%5,%6,%7}, {%8,%9}, {%0,%1,%2,%3};"
        : "+f"(c[0]), "+f"(c[1]), "+f"(c[2]), "+f"(c[3])
        : "r"(a[0]), "r"(a[1]), "r"(a[2]), "r"(a[3]), "r"(b[0]), "r"(b[1]));
}

// ---------------- CSR build ----------------
__global__ void zero_counts_kernel() {
    int i = blockIdx.x * blockDim.x + threadIdx.x;
    if (i < TOTN) g_count[i] = 0;
    if (i == 0) g_done = 0;
}

// edge_index is int32 on device (JAX x64 disabled -> astype(int64) is a no-op)
__global__ void hist_kernel(const int* __restrict__ ei0, const int* __restrict__ ei1) {
    int e = blockIdx.x * blockDim.x + threadIdx.x;
    if (e >= TOTE) return;
    int layer = (e >= NE);
    const int* ei = layer ? ei1 : ei0;
    int le = e - layer * NE;
    atomicAdd(&g_count[layer * NN + ei[NE + le]], 1);
}

// per-block reduce -> g_partial; LAST block also scans the partials (fused scanB)
__global__ void scanA_kernel() {
    int tid = threadIdx.x;
    int i = blockIdx.x * 1024 + tid;
    int v = (i < TOTN) ? g_count[i] : 0;
    #pragma unroll
    for (int o = 16; o > 0; o >>= 1) v += __shfl_down_sync(0xffffffffu, v, o);
    __shared__ int ws[32];
    if ((tid & 31) == 0) ws[tid >> 5] = v;
    __syncthreads();
    if (tid < 32) {
        int t = ws[tid];
        #pragma unroll
        for (int o = 16; o > 0; o >>= 1) t += __shfl_down_sync(0xffffffffu, t, o);
        if (tid == 0) g_partial[blockIdx.x] = t;
    }
    // last-block-done: the final block to finish scans the 98 partials in place
    __shared__ int isLast;
    __threadfence();
    if (tid == 0) isLast = (atomicAdd(&g_done, 1) == gridDim.x - 1);
    __syncthreads();
    if (isLast) {
        __shared__ int s[128];
        int pv = (tid < 128 && tid < NB) ? g_partial[tid] : 0;
        if (tid < 128) s[tid] = pv;
        __syncthreads();
        #pragma unroll
        for (int o = 1; o < 128; o <<= 1) {
            int t = (tid < 128 && tid >= o) ? s[tid - o] : 0;
            __syncthreads();
            if (tid < 128) s[tid] += t;
            __syncthreads();
        }
        if (tid < 128 && tid < NB) g_partial[tid] = s[tid] - pv;   // exclusive offsets
    }
}

__global__ void scanC_kernel() {   // block-local exclusive scan + offset -> start/cursor
    int tid = threadIdx.x;
    int i = blockIdx.x * 1024 + tid;
    int v = (i < TOTN) ? g_count[i] : 0;
    int lane = tid & 31, wid = tid >> 5;
    int incl = v;
    #pragma unroll
    for (int o = 1; o < 32; o <<= 1) {
        int y = __shfl_up_sync(0xffffffffu, incl, o);
        if (lane >= o) incl += y;
    }
    __shared__ int wsum[32];
    if (lane == 31) wsum[wid] = incl;
    __syncthreads();
    if (tid < 32) {
        int w = wsum[tid];
        #pragma unroll
        for (int o = 1; o < 32; o <<= 1) {
            int y = __shfl_up_sync(0xffffffffu, w, o);
            if (tid >= o) w += y;
        }
        wsum[tid] = w;
    }
    __syncthreads();
    int excl = incl - v + (wid ? wsum[wid - 1] : 0) + g_partial[blockIdx.x];
    if (i < TOTN) { g_start[i] = excl; g_cursor[i] = excl; }
    if (i == 0) g_start[TOTN] = TOTE;
}

// lean scatter: only (src, eid) goes into CSR order; attrs stay in place, read by eid later
__global__ void scatter_kernel(const int* __restrict__ ei0, const int* __restrict__ ei1) {
    int e = blockIdx.x * blockDim.x + threadIdx.x;
    if (e >= TOTE) return;
    int layer = (e >= NE);
    const int* ei = layer ? ei1 : ei0;
    int le = e - layer * NE;
    int dst = ei[NE + le];
    int pos = atomicAdd(&g_cursor[layer * NN + dst], 1);
    g_se_sorted[pos] = make_int2(ei[le], le);
}

// ---------------- per-node edge aggregation: f32x2 channel pairs + 2-deep prefetch ----
// 32 threads per node; thread t owns channels 2t, 2t+1 -> output dims 6t..6t+5.
#define EDGE_FMA_BLOCK()                                                        \
    do {                                                                        \
        ull a0 = pack2(p0.x, p0.x), a1 = pack2(p0.y, p0.y);                     \
        ull a2 = pack2(p1.x, p1.x), a3 = pack2(p1.y, p1.y);                     \
        ull a4 = pack2(p2.x, p2.x), a5 = pack2(p2.y, p2.y);                     \
        ull s0 = b0p, s1 = b1p, s2 = b2p;                                       \
        fma2(s0, a0, w0p[0]); fma2(s0, a1, w0p[1]); fma2(s0, a2, w0p[2]);       \
        fma2(s0, a3, w0p[3]); fma2(s0, a4, w0p[4]); fma2(s0, a5, w0p[5]);       \
        fma2(s1, a0, w1p[0]); fma2(s1, a1, w1p[1]); fma2(s1, a2, w1p[2]);       \
        fma2(s1, a3, w1p[3]); fma2(s1, a4, w1p[4]); fma2(s1, a5, w1p[5]);       \
        fma2(s2, a0, w2p[0]); fma2(s2, a1, w2p[1]); fma2(s2, a2, w2p[2]);       \
        fma2(s2, a3, w2p[3]); fma2(s2, a4, w2p[4]); fma2(s2, a5, w2p[5]);       \
        fma2(acc0, relu2(s0), xp);                                              \
        fma2(acc1, relu2(s1), xp);                                              \
        fma2(acc2, relu2(s2), xp);                                              \
    } while (0)

__global__ void __launch_bounds__(256, 3) edge_aggr_kernel(
    const float* __restrict__ x,
    const float* __restrict__ ea0, const float* __restrict__ ea1,
    const float* __restrict__ Win0, const float* __restrict__ bin0,
    const float* __restrict__ Win1, const float* __restrict__ bin1)
{
    int nid = blockIdx.x * 8 + (threadIdx.x >> 5);   // 0..TOTN-1 (TOTN % 8 == 0)
    int t = threadIdx.x & 31;
    int layer = (nid >= NN);
    const float* W_in = layer ? Win1 : Win0;
    const float* b_in = layer ? bin1 : bin0;
    const float* eab  = layer ? ea1 : ea0;

    // packed weights: wp[j][a] = (W[a][6t+j], W[a][6t+3+j])
    ull w0p[6], w1p[6], w2p[6];
    #pragma unroll
    for (int a = 0; a < 6; a++) {
        const float* Wr = W_in + a * KDIM + 6 * t;
        w0p[a] = pack2(Wr[0], Wr[3]);
        w1p[a] = pack2(Wr[1], Wr[4]);
        w2p[a] = pack2(Wr[2], Wr[5]);
    }
    const float* br = b_in + 6 * t;
    ull b0p = pack2(br[0], br[3]);
    ull b1p = pack2(br[1], br[4]);
    ull b2p = pack2(br[2], br[5]);

    int sidx = g_start[nid], eEnd = g_start[nid + 1];

    ull acc0 = 0ull, acc1 = 0ull, acc2 = 0ull;
    if (sidx < eEnd) {
        int2 se = __ldg(&g_se_sorted[sidx]);
        const float2* ea = (const float2*)(eab + (size_t)se.y * 6);
        float2 p0 = __ldg(&ea[0]), p1 = __ldg(&ea[1]), p2 = __ldg(&ea[2]);
        for (int i = sidx; i + 1 < eEnd; i++) {
            int2 se_n = __ldg(&g_se_sorted[i + 1]);          // prefetch next (src,eid)
            ull xp = *reinterpret_cast<const ull*>(x + (size_t)se.x * CIN + 2 * t);
            const float2* ean = (const float2*)(eab + (size_t)se_n.y * 6);
            float2 q0 = __ldg(&ean[0]), q1 = __ldg(&ean[1]), q2 = __ldg(&ean[2]); // prefetch next attrs
            EDGE_FMA_BLOCK();
            se = se_n; p0 = q0; p1 = q1; p2 = q2;
        }
        // final (already-prefetched) edge
        ull xp = *reinterpret_cast<const ull*>(x + (size_t)se.x * CIN + 2 * t);
        EDGE_FMA_BLOCK();
    }

    float lo0, hi0, lo1, hi1, lo2, hi2;
    unpack2(acc0, lo0, hi0);
    unpack2(acc1, lo1, hi1);
    unpack2(acc2, lo2, hi2);
    float* o = g_aggr + (size_t)nid * KDIM + 6 * t;
    o[0] = lo0; o[1] = lo1; o[2] = lo2;
    o[3] = hi0; o[4] = hi1; o[5] = hi2;
}

// ---------------- output GEMM + bias + tanh: tf32 tensor-core MMA ----------------
// block tile 128x128, BK=32, 256 threads = 8 warps as 2(m) x 4(n); warp tile 64x32.
__global__ void __launch_bounds__(256) gemm_mma_kernel(
    const float* __restrict__ Wout0, const float* __restrict__ bout0,
    const float* __restrict__ Wout1, const float* __restrict__ bout1,
    float* __restrict__ out)
{
    int layer = blockIdx.y;
    const float* Wout = layer ? Wout1 : Wout0;
    const float* bout = layer ? bout1 : bout0;
    const float* aggr = g_aggr + (size_t)layer * NN * KDIM;

    __shared__ uint32_t As[128][36];   // [row][kk] tf32 bits
    __shared__ uint32_t Bs[128][36];   // [col][kk] tf32 bits (W transposed)

    int tid  = threadIdx.x;
    int lane = tid & 31;
    int warp = tid >> 5;
    int g    = lane >> 2;
    int tig  = lane & 3;
    int wm   = (warp & 1) * 64;
    int wn   = (warp >> 1) * 32;
    int n0   = blockIdx.x * 128;

    float c[4][4][4];
    #pragma unroll
    for (int fm = 0; fm < 4; fm++)
        #pragma unroll
        for (int fn = 0; fn < 4; fn++)
            #pragma unroll
            for (int k = 0; k < 4; k++) c[fm][fn][k] = 0.f;

    for (int k0 = 0; k0 < KDIM; k0 += 32) {
        #pragma unroll
        for (int j = 0; j < 16; j++) {
            int idx = tid + 256 * j;
            int r = idx >> 5, kk = idx & 31;
            int n = n0 + r;
            float v = (n < NN) ? aggr[(size_t)n * KDIM + k0 + kk] : 0.f;
            As[r][kk] = f2tf32(v);
        }
        #pragma unroll
        for (int j = 0; j < 16; j++) {
            int idx = tid + 256 * j;
            int kk = idx >> 7, cc = idx & 127;
            Bs[cc][kk] = f2tf32(Wout[(k0 + kk) * COUT + cc]);
        }
        __syncthreads();
        #pragma unroll
        for (int ks = 0; ks < 4; ks++) {
            int kb = ks * 8;
            uint32_t a[4][4], b[4][2];
            #pragma unroll
            for (int fm = 0; fm < 4; fm++) {
                int r = wm + fm * 16 + g;
                a[fm][0] = As[r][kb + tig];
                a[fm][1] = As[r + 8][kb + tig];
                a[fm][2] = As[r][kb + tig + 4];
                a[fm][3] = As[r + 8][kb + tig + 4];
            }
            #pragma unroll
            for (int fn = 0; fn < 4; fn++) {
                int nidx = wn + fn * 8 + g;
                b[fn][0] = Bs[nidx][kb + tig];
                b[fn][1] = Bs[nidx][kb + tig + 4];
            }
            #pragma unroll
            for (int fm = 0; fm < 4; fm++)
                #pragma unroll
                for (int fn = 0; fn < 4; fn++)
                    mma_tf32(c[fm][fn], a[fm], b[fn]);
        }
        __syncthreads();
    }

    #pragma unroll
    for (int fn = 0; fn < 4; fn++) {
        int col = wn + fn * 8 + 2 * tig;
        float bv0 = bout[col], bv1 = bout[col + 1];
        #pragma unroll
        for (int fm = 0; fm < 4; fm++) {
            int r0 = n0 + wm + fm * 16 + g;
            size_t base = (size_t)layer * COUT + col;
            if (r0 < NN) {
                out[(size_t)r0 * (2 * COUT) + base]     = tanh_fast(c[fm][fn][0] + bv0);
                out[(size_t)r0 * (2 * COUT) + base + 1] = tanh_fast(c[fm][fn][1] + bv1);
            }
            if (r0 + 8 < NN) {
                out[(size_t)(r0 + 8) * (2 * COUT) + base]     = tanh_fast(c[fm][fn][2] + bv0);
                out[(size_t)(r0 + 8) * (2 * COUT) + base + 1] = tanh_fast(c[fm][fn][3] + bv1);
            }
        }
    }
}

extern "C" void kernel_launch(void* const* d_in, const int* in_sizes, int n_in,
                              void* d_out, int out_size) {
    const float* x     = (const float*)d_in[0];
    const int*   ei0   = (const int*)d_in[1];
    const float* ea0   = (const float*)d_in[2];
    const int*   ei1   = (const int*)d_in[3];
    const float* ea1   = (const float*)d_in[4];
    const float* Win0  = (const float*)d_in[5];
    const float* bin0  = (const float*)d_in[6];
    const float* Wout0 = (const float*)d_in[7];
    const float* bout0 = (const float*)d_in[8];
    const float* Win1  = (const float*)d_in[9];
    const float* bin1  = (const float*)d_in[10];
    const float* Wout1 = (const float*)d_in[11];
    const float* bout1 = (const float*)d_in[12];
    float* out = (float*)d_out;
    (void)in_sizes; (void)n_in; (void)out_size;

    zero_counts_kernel<<<(TOTN + 255) / 256, 256>>>();
    hist_kernel<<<(TOTE + 255) / 256, 256>>>(ei0, ei1);
    scanA_kernel<<<NB, 1024>>>();           // includes fused partial-scan (last block)
    scanC_kernel<<<NB, 1024>>>();
    scatter_kernel<<<(TOTE + 255) / 256, 256>>>(ei0, ei1);

    edge_aggr_kernel<<<TOTN / 8, 256>>>(x, ea0, ea1, Win0, bin0, Win1, bin1);

    dim3 ggrid((NN + 127) / 128, 2);
    gemm_mma_kernel<<<ggrid, 256>>>(Wout0, bout0, Wout1, bout1, out);
}